// round 7
// baseline (speedup 1.0000x reference)
#include <cuda_runtime.h>

// ComNet: R=64 runs, T=256 timesteps, N=1024 agents, MLP 4->10(tanh)->2.
// Wavefront over B=4 agent blocks: thread t computes block b = s - 2t at step
// s, for TWO independent runs (latency hiding via cross-run ILP).
// Intra-warp handoff via shuffles; warp boundary via 3-deep smem ring +
// one __syncthreads per step. Math: packed fma.rn.f32x2 + MUFU tanh.

#define R_ 64
#define T_ 256
#define N_ 1024
#define NB_ 256                       // blocks per row (N/4)
#define NSTEP_ (2 * (T_ - 1) + NB_)   // 766 wavefront steps
#define U_ 2                          // runs per CTA

typedef unsigned long long ull;

__device__ __forceinline__ float htanh(float x) {
    float r; asm("tanh.approx.f32 %0, %1;" : "=f"(r) : "f"(x)); return r;
}
__device__ __forceinline__ ull pk(float lo, float hi) {
    ull r; asm("mov.b64 %0, {%1, %2};" : "=l"(r) : "f"(lo), "f"(hi)); return r;
}
__device__ __forceinline__ void upk(float& lo, float& hi, ull v) {
    asm("mov.b64 {%0, %1}, %2;" : "=f"(lo), "=f"(hi) : "l"(v));
}
__device__ __forceinline__ ull fma2(ull a, ull b, ull c) {
    ull d; asm("fma.rn.f32x2 %0, %1, %2, %3;" : "=l"(d) : "l"(a), "l"(b), "l"(c));
    return d;
}

__global__ __launch_bounds__(256, 1)
void comnet_kernel(const float* __restrict__ runs,
                   const float* __restrict__ comm0,
                   const float* __restrict__ w1,
                   const float* __restrict__ b1,
                   const float* __restrict__ w2,
                   const float* __restrict__ b2,
                   float* __restrict__ out)
{
    const int rbase = blockIdx.x * U_;
    const int t     = threadIdx.x;
    const int lane  = t & 31;
    const int warp  = t >> 5;

    // warp-boundary exchange ring, per run
    __shared__ float4 ring[3][8][U_];

    // ---- packed weights in registers (pair p = hidden units 2p, 2p+1) ----
    ull W1p[20], B1p[5], W2a[5], W2b[5];
#pragma unroll
    for (int p = 0; p < 5; ++p) {
#pragma unroll
        for (int q = 0; q < 4; ++q)
            W1p[4 * p + q] = pk(w1[4 * (2 * p) + q], w1[4 * (2 * p + 1) + q]);
        B1p[p] = pk(b1[2 * p], b1[2 * p + 1]);
        W2a[p] = pk(w2[2 * p],      w2[2 * p + 1]);
        W2b[p] = pk(w2[10 + 2 * p], w2[10 + 2 * p + 1]);
    }
    const ull B2lo0 = pk(b2[0], 0.0f);
    const ull B2hi0 = pk(b2[1], 0.0f);

    const float4* __restrict__ xrow4[U_];
    float4*       __restrict__ orow4[U_];
    const float*  __restrict__ c0row[U_];
#pragma unroll
    for (int u = 0; u < U_; ++u) {
        xrow4[u] = (const float4*)(runs + ((size_t)(rbase + u) * T_ + t) * (size_t)N_ * 2);
        orow4[u] = (float4*)(out + ((size_t)(rbase + u) * T_ + t) * N_);
        c0row[u] = comm0 + (size_t)(rbase + u) * N_;
    }

    float4 h1[U_], h2[U_], px0[U_], px1[U_], pc0[U_];
#pragma unroll
    for (int u = 0; u < U_; ++u) {
        h1[u] = make_float4(0.f, 0.f, 0.f, 0.f);
        h2[u] = h1[u]; px0[u] = h1[u]; px1[u] = h1[u]; pc0[u] = h1[u];
    }
    if (t == 0) {
#pragma unroll
        for (int u = 0; u < U_; ++u) {
            px0[u] = xrow4[u][0];
            px1[u] = xrow4[u][1];
            pc0[u] = make_float4(c0row[u][1], c0row[u][2], c0row[u][3], c0row[u][4]);
        }
    }

    // rotating ring phases: p2=(s-2)%3, p1=(s-1)%3, p0=s%3
    int p0 = 0, p1 = 2, p2 = 1;

    for (int s = 0; s < NSTEP_; ++s) {
        const int b = s - 2 * t;
        const bool active = ((unsigned)b < (unsigned)NB_);

        // ---- right values c(t-1, 4b+1..4b+4), both runs ----
        float rv[U_][4];
#pragma unroll
        for (int u = 0; u < U_; ++u) {
            rv[u][0] = __shfl_up_sync(0xffffffffu, h2[u].y, 1);
            rv[u][1] = __shfl_up_sync(0xffffffffu, h2[u].z, 1);
            rv[u][2] = __shfl_up_sync(0xffffffffu, h2[u].w, 1);
            rv[u][3] = __shfl_up_sync(0xffffffffu, h1[u].x, 1);
        }
        if (lane == 0) {
            const int pw = (warp > 0) ? (warp - 1) : 0;
#pragma unroll
            for (int u = 0; u < U_; ++u) {
                float4 g2 = ring[p2][pw][u];
                float4 g1 = ring[p1][pw][u];
                rv[u][0] = g2.y; rv[u][1] = g2.z; rv[u][2] = g2.w; rv[u][3] = g1.x;
            }
        }
        if (t == 0) {
#pragma unroll
            for (int u = 0; u < U_; ++u) {
                rv[u][0] = pc0[u].x; rv[u][1] = pc0[u].y;
                rv[u][2] = pc0[u].z; rv[u][3] = pc0[u].w;
            }
        }
        if (b == NB_ - 1) {
#pragma unroll
            for (int u = 0; u < U_; ++u) rv[u][3] = 0.0f;
        }

        float4 cx0[U_], cx1[U_];
#pragma unroll
        for (int u = 0; u < U_; ++u) { cx0[u] = px0[u]; cx1[u] = px1[u]; }

        // ---- prefetch next step's block inputs ----
        const int bn = s + 1 - 2 * t;
        if ((unsigned)bn < (unsigned)NB_) {
#pragma unroll
            for (int u = 0; u < U_; ++u) {
                px0[u] = xrow4[u][2 * bn];
                px1[u] = xrow4[u][2 * bn + 1];
            }
            if (t == 0) {
                const int base = 4 * bn;
#pragma unroll
                for (int u = 0; u < U_; ++u)
                    pc0[u] = make_float4(c0row[u][base + 1], c0row[u][base + 2],
                                         c0row[u][base + 3],
                                         (bn < NB_ - 1) ? c0row[u][base + 4] : 0.0f);
            }
        }

        float4 cur[U_];
#pragma unroll
        for (int u = 0; u < U_; ++u) cur[u] = h1[u];

        if (active) {
            float o0v[U_][4], o1v[U_][4], lf[U_];
#pragma unroll
            for (int u = 0; u < U_; ++u) lf[u] = (b == 0) ? 0.0f : h1[u].w;

#pragma unroll
            for (int k = 0; k < 4; ++k) {
#pragma unroll
                for (int u = 0; u < U_; ++u) {   // two independent chains -> ILP
                    const float xx = (k == 0) ? cx0[u].x : (k == 1) ? cx0[u].z
                                    : (k == 2) ? cx1[u].x : cx1[u].z;
                    const float xy = (k == 0) ? cx0[u].y : (k == 1) ? cx0[u].w
                                    : (k == 2) ? cx1[u].y : cx1[u].w;
                    const float rt = rv[u][k];

                    const ull xx2 = pk(xx, xx);
                    const ull xy2 = pk(xy, xy);
                    const ull rt2 = pk(rt, rt);
                    const ull lf2 = pk(lf[u], lf[u]);

                    ull A0 = B2lo0, A1 = B2hi0;
#pragma unroll
                    for (int p = 0; p < 5; ++p) {
                        ull a = fma2(W1p[4 * p + 0], xx2, B1p[p]);
                        a     = fma2(W1p[4 * p + 1], xy2, a);
                        a     = fma2(W1p[4 * p + 3], rt2, a);
                        a     = fma2(W1p[4 * p + 2], lf2, a);   // lf last: shortest chain
                        float alo, ahi; upk(alo, ahi, a);
                        const ull hh = pk(htanh(alo), htanh(ahi));
                        A0 = fma2(W2a[p], hh, A0);
                        A1 = fma2(W2b[p], hh, A1);
                    }
                    float a0l, a0h, a1l, a1h;
                    upk(a0l, a0h, A0);
                    upk(a1l, a1h, A1);
                    o0v[u][k] = a0l + a0h;
                    const float o1 = a1l + a1h;
                    o1v[u][k] = o1;
                    lf[u] = o1;                   // left-chain within block
                }
            }
#pragma unroll
            for (int u = 0; u < U_; ++u) {
                orow4[u][b] = make_float4(o0v[u][0], o0v[u][1], o0v[u][2], o0v[u][3]);
                cur[u] = make_float4(o1v[u][0], o1v[u][1], o1v[u][2], o1v[u][3]);
            }
        }

        // publish warp-boundary blocks; shift history
        if (lane == 31 && active) {
#pragma unroll
            for (int u = 0; u < U_; ++u) ring[p0][warp][u] = cur[u];
        }
#pragma unroll
        for (int u = 0; u < U_; ++u) {
            h2[u] = h1[u];
            if (active) h1[u] = cur[u];
        }

        // rotate ring phases
        const int pn = p2;
        p2 = p1; p1 = p0; p0 = pn;

        __syncthreads();
    }
}

extern "C" void kernel_launch(void* const* d_in, const int* in_sizes, int n_in,
                              void* d_out, int out_size)
{
    const float* runs  = (const float*)d_in[0];
    const float* comm0 = (const float*)d_in[1];
    const float* w1    = (const float*)d_in[2];
    const float* b1    = (const float*)d_in[3];
    const float* w2    = (const float*)d_in[4];
    const float* b2    = (const float*)d_in[5];
    float* out = (float*)d_out;

    comnet_kernel<<<R_ / U_, 256>>>(runs, comm0, w1, b1, w2, b2, out);
}